// round 16
// baseline (speedup 1.0000x reference)
#include <cuda_runtime.h>
#include <cstdint>

// Problem dims
#define T_DIM 32
#define B_DIM 64
#define D_DIM 256
#define P_DIM 1024
#define M_TOT (T_DIM * B_DIM)   // 2048
#define KNOTS 17

// Scratch (static device globals — no runtime allocation)
__device__ float g_partial[256];
__device__ int   g_count = 0;

// RNA(f32 -> tf32) == truncate(bits + 0x1000)
#define RNA_BIAS 0x1000u

typedef unsigned long long u64;
#define SGN_BOTH 0x8000000080000000ULL

#define FMA_F32X2(d, a, b, c) \
    asm("fma.rn.f32x2 %0, %1, %2, %3;" : "=l"(d) : "l"(a), "l"(b), "l"(c))
#define ADD_F32X2(d, a, b) \
    asm("add.rn.f32x2 %0, %1, %2;" : "=l"(d) : "l"(a), "l"(b))
#define PACK2(d, lo, hi) \
    asm("mov.b64 %0, {%1, %2};" : "=l"(d) : "r"(__float_as_uint(lo)), "r"(__float_as_uint(hi)))
#define UNPACK2(lo, hi, s) \
    do { unsigned _l, _h; \
         asm("mov.b64 {%0, %1}, %2;" : "=r"(_l), "=r"(_h) : "l"(s)); \
         lo = __uint_as_float(_l); hi = __uint_as_float(_h); } while (0)

// phi_k = exp(-(k*dt)^2/2), dt = 3/16
__device__ const float PHI_TAB[16] = {
    0.9825755f, 0.9321025f, 0.8536763f, 0.7548390f,
    0.6443885f, 0.5310960f, 0.4226005f, 0.3246525f,
    0.2407901f, 0.1724217f, 0.1191997f, 0.0795592f,
    0.0512672f, 0.0318948f, 0.0191572f, 0.0111090f
};

// ---------------------------------------------------------------------------
// Single fused kernel, SMALL-TILE (2 blocks/SM) version:
// M-tile 64 = ONE t-group x full 64-b range.  Grid (8 n-blocks, 32 t) = 256
// blocks, ~102 KB SMEM each -> 2 co-resident blocks/SM, 16 warps/SM.
// GEMM mainloop (tf32 HMMA, RNA bias) -> in-block col norms -> SMEM x-tile ->
// packed-Chebyshev trig epilogue (2 b-halves/col) -> fused final reduction.
// ---------------------------------------------------------------------------
#define ASTRIDE 68
#define BSTRIDE 136
#define CHUNKA_F (64 * ASTRIDE)              // 4352 floats
#define CHUNKB_F (64 * BSTRIDE)              // 8704 floats
#define GEMM_SMEM ((2 * CHUNKA_F + 2 * CHUNKB_F) * 4)   // 104448 B

// Epilogue SMEM layout (reuses chunk region):
#define XT_STRIDE 132
#define XT_F      (64 * XT_STRIDE)           // 8448 floats
#define INV_OFF   XT_F                       // [128] inv norms
#define NSCR_OFF  (XT_F + 128)               // [128] norm scratch
#define MRG_OFF   (XT_F + 256)               // [16][128][2] half-merge = 4096
#define RED_OFF   (XT_F + 256 + 4096)        // [256]

__device__ __forceinline__ void load_chunk(
    uint32_t sb, int buf, int kt, int m0, int n0,
    const float4* __restrict__ pa, const float4* __restrict__ pb, int tid)
{
    // A tile: 64 rows (m) x 16 float4 (k) = 1024 float4
    #pragma unroll
    for (int t = 0; t < 4; ++t) {
        int idx = t * 256 + tid;
        int row = idx >> 4;                 // 0..63
        int c   = idx & 15;
        uint32_t off = (uint32_t)((buf * CHUNKA_F + row * ASTRIDE + c * 4) * 4);
        const float4* s = pa + (size_t)(m0 + row) * (D_DIM / 4) + kt * 16 + c;
        asm volatile("cp.async.cg.shared.global [%0], [%1], 16;"
                     :: "r"(sb + off), "l"(s));
    }
    // B tile: 64 rows (k=d) x 32 float4 (n) = 2048 float4
    #pragma unroll
    for (int t = 0; t < 8; ++t) {
        int idx = t * 256 + tid;
        int row = idx >> 5;                 // 0..63
        int c   = idx & 31;
        uint32_t off = (uint32_t)((2 * CHUNKA_F + buf * CHUNKB_F
                                   + row * BSTRIDE + c * 4) * 4);
        const float4* s = pb + (size_t)(kt * 64 + row) * (P_DIM / 4) + n0 / 4 + c;
        asm volatile("cp.async.cg.shared.global [%0], [%1], 16;"
                     :: "r"(sb + off), "l"(s));
    }
}

__global__ __launch_bounds__(256, 2) void fused_kernel(
    const float* __restrict__ pA, const float* __restrict__ pB,
    float* __restrict__ out)
{
    extern __shared__ float sm[];
    uint32_t sb;
    asm("{ .reg .u64 t; cvta.to.shared.u64 t, %1; cvt.u32.u64 %0, t; }"
        : "=r"(sb) : "l"(sm));

    const int tid = threadIdx.x;
    const int wid = tid >> 5;
    const int lid = tid & 31;
    const int gid = lid >> 2;
    const int tig = lid & 3;
    const int wm  = (wid >> 2) * 32;       // 2 warp-rows of 32
    const int wn  = (wid & 3) * 32;        // 4 warp-cols of 32
    const int m0  = blockIdx.y * 64;       // one t-group
    const int n0  = blockIdx.x * 128;
    const int ncol = tid & 127;
    const int nhalf = tid >> 7;

    const float4* pa = (const float4*)pA;
    const float4* pb = (const float4*)pB;

    float acc[2][4][4];
    #pragma unroll
    for (int mi = 0; mi < 2; ++mi)
        #pragma unroll
        for (int ni = 0; ni < 4; ++ni)
            #pragma unroll
            for (int r = 0; r < 4; ++r) acc[mi][ni][r] = 0.f;
    float nsq = 0.f;

    load_chunk(sb, 0, 0, m0, n0, pa, pb, tid);
    asm volatile("cp.async.commit_group;" ::: "memory");

    #pragma unroll
    for (int kt = 0; kt < 4; ++kt) {
        if (kt < 3) {
            load_chunk(sb, (kt + 1) & 1, kt + 1, m0, n0, pa, pb, tid);
            asm volatile("cp.async.commit_group;" ::: "memory");
            asm volatile("cp.async.wait_group 1;" ::: "memory");
        } else {
            asm volatile("cp.async.wait_group 0;" ::: "memory");
        }
        __syncthreads();

        const int buf = kt & 1;
        const float* As = sm + buf * CHUNKA_F;
        const float* Bs = sm + 2 * CHUNKA_F + buf * CHUNKB_F;

        // Column sum-of-squares (B panel covers all 256 k rows over 4 chunks)
        {
            const float* np = Bs + nhalf * 32 * BSTRIDE + ncol;
            #pragma unroll
            for (int j = 0; j < 32; ++j) {
                float v = np[j * BSTRIDE];
                nsq += v * v;
            }
        }

        #pragma unroll
        for (int ks = 0; ks < 8; ++ks) {
            const int kc = ks * 8;
            uint32_t a[2][4];
            #pragma unroll
            for (int mi = 0; mi < 2; ++mi) {
                const float* ap = As + (wm + mi * 16 + gid) * ASTRIDE + kc + tig;
                a[mi][0] = __float_as_uint(ap[0])               + RNA_BIAS;
                a[mi][1] = __float_as_uint(ap[8 * ASTRIDE])     + RNA_BIAS;
                a[mi][2] = __float_as_uint(ap[4])               + RNA_BIAS;
                a[mi][3] = __float_as_uint(ap[8 * ASTRIDE + 4]) + RNA_BIAS;
            }
            uint32_t b[4][2];
            #pragma unroll
            for (int ni = 0; ni < 4; ++ni) {
                const float* bp = Bs + (kc + tig) * BSTRIDE + wn + ni * 8 + gid;
                b[ni][0] = __float_as_uint(bp[0])               + RNA_BIAS;
                b[ni][1] = __float_as_uint(bp[4 * BSTRIDE])     + RNA_BIAS;
            }
            #pragma unroll
            for (int mi = 0; mi < 2; ++mi)
                #pragma unroll
                for (int ni = 0; ni < 4; ++ni)
                    asm volatile(
                        "mma.sync.aligned.m16n8k8.row.col.f32.tf32.tf32.f32 "
                        "{%0,%1,%2,%3}, {%4,%5,%6,%7}, {%8,%9}, {%0,%1,%2,%3};"
                        : "+f"(acc[mi][ni][0]), "+f"(acc[mi][ni][1]),
                          "+f"(acc[mi][ni][2]), "+f"(acc[mi][ni][3])
                        : "r"(a[mi][0]), "r"(a[mi][1]), "r"(a[mi][2]), "r"(a[mi][3]),
                          "r"(b[ni][0]), "r"(b[ni][1]));
        }
        __syncthreads();
    }

    // ---- Norm combine ----
    if (nhalf == 1) sm[NSCR_OFF + ncol] = nsq;
    __syncthreads();
    if (nhalf == 0) {
        float tot = nsq + sm[NSCR_OFF + ncol];
        sm[INV_OFF + ncol] = 1.f / fmaxf(sqrtf(tot), 1e-12f);
    }

    // ---- Phase A: spill acc fragments to SMEM x-tile [m=64][n=128] ----
    #pragma unroll
    for (int mi = 0; mi < 2; ++mi) {
        const int m = wm + mi * 16 + gid;
        #pragma unroll
        for (int ni = 0; ni < 4; ++ni) {
            const int n = wn + ni * 8 + tig * 2;
            float2 v0 = { acc[mi][ni][0], acc[mi][ni][1] };
            float2 v1 = { acc[mi][ni][2], acc[mi][ni][3] };
            *(float2*)&sm[m * XT_STRIDE + n]       = v0;
            *(float2*)&sm[(m + 8) * XT_STRIDE + n] = v1;
        }
    }
    __syncthreads();

    // ---- Phase B: 2 threads per col (b-halves of 32): packed Chebyshev ----
    const int bh  = tid >> 7;            // 0/1: b half
    const int col = tid & 127;
    const float dt = 3.0f / 16.0f;
    const float sc = dt * sm[INV_OFF + col];

    u64 kacc[KNOTS - 1];
    #pragma unroll
    for (int k = 0; k < KNOTS - 1; ++k) kacc[k] = 0ull;

    const float* xrow = sm + bh * 32 * XT_STRIDE + col;
    #pragma unroll 2
    for (int b = 0; b < 32; ++b) {
        float x = xrow[b * XT_STRIDE];
        float s1, c1;
        __sincosf(x * sc, &s1, &c1);
        const float tc = 2.f * c1;
        u64 cur, prev, tc2;
        PACK2(cur, c1, s1);
        PACK2(prev, 1.f, 0.f);
        PACK2(tc2, tc, tc);
        #pragma unroll
        for (int k = 0; k < KNOTS - 1; ++k) {
            ADD_F32X2(kacc[k], kacc[k], cur);
            u64 np = prev ^ SGN_BOTH;
            u64 nxt;
            FMA_F32X2(nxt, tc2, cur, np);
            prev = cur; cur = nxt;
        }
    }

    __syncthreads();   // x-tile reads done before merge region reuse is safe

    // Merge half 1 into half 0
    if (bh == 1) {
        #pragma unroll
        for (int k = 0; k < KNOTS - 1; ++k) {
            float cv, sv;
            UNPACK2(cv, sv, kacc[k]);
            sm[MRG_OFF + (k * 128 + col) * 2 + 0] = cv;
            sm[MRG_OFF + (k * 128 + col) * 2 + 1] = sv;
        }
    }
    __syncthreads();

    float val = 0.f;
    if (bh == 0) {
        const float invB = 1.f / (float)B_DIM;
        #pragma unroll
        for (int k = 1; k <= 16; ++k) {
            float phik = PHI_TAB[k - 1];
            float wk   = ((k == 16) ? dt : 2.f * dt) * phik;
            float cs, ss;
            UNPACK2(cs, ss, kacc[k - 1]);
            cs += sm[MRG_OFF + ((k - 1) * 128 + col) * 2 + 0];
            ss += sm[MRG_OFF + ((k - 1) * 128 + col) * 2 + 1];
            float cm = cs * invB - phik;
            float smn = ss * invB;
            val += wk * (cm * cm + smn * smn);
        }
        val *= (float)B_DIM;
    }

    // ---- Block reduction + fused deterministic final reduction ----
    float* red = sm + RED_OFF;
    red[tid] = val;
    __syncthreads();
    #pragma unroll
    for (int s = 128; s > 0; s >>= 1) {
        if (tid < s) red[tid] += red[tid + s];
        __syncthreads();
    }

    __shared__ int is_last;
    if (tid == 0) {
        g_partial[blockIdx.y * gridDim.x + blockIdx.x] = red[0];
        __threadfence();
        int prev = atomicAdd(&g_count, 1);
        is_last = (prev == (int)(gridDim.x * gridDim.y) - 1);
    }
    __syncthreads();

    if (is_last) {
        red[tid] = g_partial[tid];
        __syncthreads();
        #pragma unroll
        for (int s = 128; s > 0; s >>= 1) {
            if (tid < s) red[tid] += red[tid + s];
            __syncthreads();
        }
        if (tid == 0) {
            out[0] = red[0] * (1.0f / (float)(T_DIM * P_DIM));
            g_count = 0;   // reset so graph replays are deterministic
        }
    }
}

// ---------------------------------------------------------------------------
extern "C" void kernel_launch(void* const* d_in, const int* in_sizes, int n_in,
                              void* d_out, int out_size)
{
    const float* proj = (const float*)d_in[0];   // (32,64,256)
    const float* Amat = (const float*)d_in[1];   // (256,1024)
    float* out = (float*)d_out;

    cudaFuncSetAttribute(fused_kernel, cudaFuncAttributeMaxDynamicSharedMemorySize,
                         GEMM_SMEM);

    dim3 g1(P_DIM / 128, T_DIM);   // (8, 32) = 256 blocks
    fused_kernel<<<g1, 256, GEMM_SMEM>>>(proj, Amat, out);
}